// round 3
// baseline (speedup 1.0000x reference)
#include <cuda_runtime.h>
#include <cuda_bf16.h>
#include <math.h>

// Problem constants (from reference_code)
#define PB  32      // episodes
#define PS  50      // n_support
#define PQ  75      // n_query
#define PT  128     // time steps
#define PF  64      // features
#define PD  256     // embedding dim
#define PK  5       // N_WAY

#define N_SUP (PB * PS)                 // 1600
#define N_QRY (PB * PQ)                 // 2400
#define N_SAMPLES (N_SUP + N_QRY)       // 4000
#define SAMPLE_FLOATS (PT * PF)         // 8192
#define SAMPLE_F4     (SAMPLE_FLOATS/4) // 2048 float4 per sample

#define NBLK 148
#define NTHR 256
#define NWARPS_TOTAL (NBLK * 8)         // 1184
#define QCHUNK 15
#define NTILES (PB * (PQ / QCHUNK))     // 160

// Scratch (device globals — no allocation allowed)
__device__ float g_xm[N_SAMPLES * PF];  // time-mean per sample [4000, 64]
__device__ volatile unsigned g_bar;     // grid barrier counter (self-resetting)
__device__ unsigned g_done;             // exit counter for reset

__global__ __launch_bounds__(NTHR) void fused_proto_kernel(
    const float* __restrict__ support_x,
    const int*   __restrict__ support_y,
    const float* __restrict__ query_x,
    const float* __restrict__ W,          // [F=64, D=256] row-major
    float*       __restrict__ out)        // [B*Q, K]
{
    const int tid  = threadIdx.x;
    const int lane = tid & 31;
    const int warp = tid >> 5;

    // ======================================================================
    // Phase 1: time-mean pooling, warp-per-sample.
    // Sample = [128,64] floats = 2048 float4.  Lane loads j = lane + 32*i,
    // i = 0..63 (64 iters * 32 lanes = 2048).  Since 32*i % 16 == 0,
    // j%16 == lane%16 is fixed per lane, so each lane always covers
    // features 4*(lane%16)..+3.  One shfl_xor(16) completes the reduce;
    // lanes 0..15 write one float4 each.
    // ======================================================================
    for (int s = blockIdx.x * 8 + warp; s < N_SAMPLES; s += NWARPS_TOTAL) {
        const float* src = (s < N_SUP)
            ? support_x + (size_t)s * SAMPLE_FLOATS
            : query_x   + (size_t)(s - N_SUP) * SAMPLE_FLOATS;
        const float4* src4 = reinterpret_cast<const float4*>(src);

        float4 a = make_float4(0.f, 0.f, 0.f, 0.f);
#pragma unroll 16
        for (int i = 0; i < SAMPLE_F4 / 32; i++) {   // 64 iterations
            float4 v = src4[lane + 32 * i];
            a.x += v.x; a.y += v.y; a.z += v.z; a.w += v.w;
        }
        a.x += __shfl_xor_sync(0xFFFFFFFFu, a.x, 16);
        a.y += __shfl_xor_sync(0xFFFFFFFFu, a.y, 16);
        a.z += __shfl_xor_sync(0xFFFFFFFFu, a.z, 16);
        a.w += __shfl_xor_sync(0xFFFFFFFFu, a.w, 16);

        if (lane < 16) {
            const float inv = 1.0f / (float)PT;
            float4 r = make_float4(a.x * inv, a.y * inv, a.z * inv, a.w * inv);
            reinterpret_cast<float4*>(g_xm)[(size_t)s * 16 + lane] = r;
        }
    }

    // ======================================================================
    // Grid barrier (release: threadfence + atomic arrive; acquire: spin +
    // threadfence; block fan-in/out via syncthreads).  148 blocks on 148
    // SMs are guaranteed co-resident (1 CTA/SM), so the spin cannot deadlock.
    // ======================================================================
    __syncthreads();
    if (tid == 0) {
        __threadfence();
        atomicAdd((unsigned*)&g_bar, 1u);
        while (g_bar < (unsigned)NBLK) { /* spin on L2 via volatile */ }
        __threadfence();
    }
    __syncthreads();

    // ======================================================================
    // Phase 2: tiles (episode b, query chunk qc).  Each tile recomputes its
    // episode's prototypes in-block (redundant x5, cheap: 50 L2 loads) and
    // then logits for its 15 queries.  Thread tid owns output dim d=tid.
    // Bias b cancels in (query_z - proto_z) so it is never loaded.
    // Cross-barrier global reads use __ldcg (L2 path; L1 not coherent).
    // ======================================================================
    __shared__ int   ys[PS];
    __shared__ float s_pxm[PK * PF];
    __shared__ float s_qxm[QCHUNK * PF];
    __shared__ float s_red[8][PK];

    for (int t = blockIdx.x; t < NTILES; t += NBLK) {
        __syncthreads();                      // protect smem from previous tile
        const int b  = t / (PQ / QCHUNK);
        const int qc = t % (PQ / QCHUNK);

        if (tid < PS) ys[tid] = support_y[b * PS + tid];
        {
            const float* qbase = g_xm + (size_t)(N_SUP + b * PQ + qc * QCHUNK) * PF;
            for (int i = tid; i < QCHUNK * PF; i += NTHR)
                s_qxm[i] = __ldcg(qbase + i);
        }
        __syncthreads();

        // in-block prototypes: thread f (<64) accumulates class means
        if (tid < PF) {
            float acc[PK], cnt[PK];
#pragma unroll
            for (int k = 0; k < PK; k++) { acc[k] = 0.f; cnt[k] = 0.f; }
            for (int s = 0; s < PS; s++) {
                const float v = __ldcg(&g_xm[(size_t)(b * PS + s) * PF + tid]);
                const int   y = ys[s];
#pragma unroll
                for (int k = 0; k < PK; k++) {
                    const bool hit = (y == k);
                    acc[k] += hit ? v : 0.f;
                    cnt[k] += hit ? 1.f : 0.f;
                }
            }
#pragma unroll
            for (int k = 0; k < PK; k++) {
                const float c = (cnt[k] > 0.f) ? cnt[k] : 1.f;
                s_pxm[k * PF + tid] = acc[k] / c;
            }
        }
        __syncthreads();

        // W column for this thread's dim (coalesced; W is L2-hot)
        float Wc[PF];
#pragma unroll
        for (int f = 0; f < PF; f++)
            Wc[f] = W[f * PD + tid];

        float pz[PK];
#pragma unroll
        for (int k = 0; k < PK; k++) {
            float s = 0.f;
#pragma unroll
            for (int f = 0; f < PF; f++)
                s += s_pxm[k * PF + f] * Wc[f];
            pz[k] = s;
        }

        for (int q = 0; q < QCHUNK; q++) {
            float zq = 0.f;
#pragma unroll
            for (int f = 0; f < PF; f++)
                zq += s_qxm[q * PF + f] * Wc[f];

            float d2[PK];
#pragma unroll
            for (int k = 0; k < PK; k++) {
                const float df = zq - pz[k];
                d2[k] = df * df;
            }
#pragma unroll
            for (int off = 16; off > 0; off >>= 1) {
#pragma unroll
                for (int k = 0; k < PK; k++)
                    d2[k] += __shfl_xor_sync(0xFFFFFFFFu, d2[k], off);
            }
            if (lane == 0) {
#pragma unroll
                for (int k = 0; k < PK; k++)
                    s_red[warp][k] = d2[k];
            }
            __syncthreads();
            if (tid < PK) {
                float s = 0.f;
#pragma unroll
                for (int w = 0; w < 8; w++)
                    s += s_red[w][tid];
                const int row = b * PQ + qc * QCHUNK + q;
                out[(size_t)row * PK + tid] = -sqrtf(s);
            }
            __syncthreads();   // s_red reused next q
        }
    }

    // ======================================================================
    // Reset barrier state for the next graph replay.  The last block to
    // arrive (old == NBLK-1) is the only writer after all others finished.
    // ======================================================================
    __syncthreads();
    if (tid == 0) {
        __threadfence();
        unsigned old = atomicAdd(&g_done, 1u);
        if (old == (unsigned)(NBLK - 1)) {
            g_bar  = 0u;
            g_done = 0u;
            __threadfence();
        }
    }
}

// ---------------------------------------------------------------------------
// Inputs (metadata order):
//   [0] support_x f32 [32,50,128,64]
//   [1] support_y i32 [32,50]
//   [2] query_x   f32 [32,75,128,64]
//   [3] W         f32 [64,256]
//   [4] b         f32 [256]       (unused — cancels in distances)
// output: f32 [2400, 5]
// ---------------------------------------------------------------------------
extern "C" void kernel_launch(void* const* d_in, const int* in_sizes, int n_in,
                              void* d_out, int out_size)
{
    const float* support_x = (const float*)d_in[0];
    const int*   support_y = (const int*)  d_in[1];
    const float* query_x   = (const float*)d_in[2];
    const float* W         = (const float*)d_in[3];
    float*       out       = (float*)d_out;

    fused_proto_kernel<<<NBLK, NTHR>>>(support_x, support_y, query_x, W, out);
}